// round 14
// baseline (speedup 1.0000x reference)
#include <cuda_runtime.h>
#include <cuda_bf16.h>
#include <cstdint>

#define S_LEN  8192
#define BH     32
#define NWIN   511
#define WTOT   (5*128*256 + 128*128)

#define M1 (BH*NWIN*8)   // 130816
#define M2 (BH*NWIN*4)   // 65408
#define M3 (BH*NWIN*2)   // 32704
#define M4 (BH*NWIN)     // 16352

__device__ __nv_bfloat16 g_w_hi[WTOT];
__device__ __nv_bfloat16 g_w_lo[WTOT];
__device__ float         g_pew[16 * 128];
__device__ __nv_bfloat16 g_a1_hi[(size_t)M1*128], g_a1_lo[(size_t)M1*128];
__device__ __nv_bfloat16 g_a2_hi[(size_t)M2*128], g_a2_lo[(size_t)M2*128];
__device__ __nv_bfloat16 g_a3_hi[(size_t)M3*128], g_a3_lo[(size_t)M3*128];

union U8b { __nv_bfloat16 b[8]; uint4 v; };
union U4b { __nv_bfloat16 b[4]; unsigned long long u; };
union U2b { __nv_bfloat16 b[2]; uint32_t u; };

// ---------------------------------------------------------------------------
// merged prep: blocks [0,704) split weights; [704,712) pew; [712,728) zero out
__global__ void prep_kernel(const float* __restrict__ wd,
                            const float* __restrict__ ws,
                            const float* __restrict__ pe,
                            float* __restrict__ out) {
    int b = blockIdx.x, tid = threadIdx.x;
    if (b < 704) {
        int i = b * 256 + tid;
        if (i < WTOT) {
            float v = (i < 5*128*256) ? wd[i] : ws[i - 5*128*256];
            __nv_bfloat16 h = __float2bfloat16(v);
            g_w_hi[i] = h;
            g_w_lo[i] = __float2bfloat16(v - __bfloat162float(h));
        }
    } else if (b < 712) {
        int idx = (b - 704) * 256 + tid;       // 2048
        int n = idx >> 4, j = idx & 15;        // coalesced wd rows per warp
        float s = 0.f;
        for (int d = 0; d < 128; ++d) {
            s += pe[(2*j)*128 + d]   * wd[n*256 + d];
            s += pe[(2*j+1)*128 + d] * wd[n*256 + 128 + d];
        }
        g_pew[j * 128 + n] = s;
    } else {
        int i = (b - 712) * 256 + tid;
        if (i < 4096)
            out[(size_t)(i >> 7) * 512 * 128 + (i & 127)] = 0.f;
    }
}

// ---------------------------------------------------------------------------
__device__ __forceinline__ uint32_t u32p(const void* p) {
    return (uint32_t)__cvta_generic_to_shared(p);
}
__device__ __forceinline__ void ldmx4(uint32_t* r, uint32_t addr) {
    asm volatile("ldmatrix.sync.aligned.m8n8.x4.shared.b16 {%0,%1,%2,%3}, [%4];"
                 : "=r"(r[0]), "=r"(r[1]), "=r"(r[2]), "=r"(r[3]) : "r"(addr));
}
__device__ __forceinline__ void mma16816(float* c, const uint32_t* a,
                                         uint32_t b0, uint32_t b1) {
    asm volatile("mma.sync.aligned.m16n8k16.row.col.f32.bf16.bf16.f32 "
                 "{%0,%1,%2,%3}, {%4,%5,%6,%7}, {%8,%9}, {%0,%1,%2,%3};"
                 : "+f"(c[0]), "+f"(c[1]), "+f"(c[2]), "+f"(c[3])
                 : "r"(a[0]), "r"(a[1]), "r"(a[2]), "r"(a[3]), "r"(b0), "r"(b1));
}
__device__ __forceinline__ float silu_f(float x) { return x / (1.f + __expf(-x)); }

__device__ __forceinline__ void cpasync16(uint32_t dst, const void* src) {
    asm volatile("cp.async.cg.shared.global [%0], [%1], 16;" :: "r"(dst), "l"(src));
}
__device__ __forceinline__ void cpasync16z(uint32_t dst, const void* src, bool v) {
    int sz = v ? 16 : 0;
    asm volatile("cp.async.cg.shared.global [%0], [%1], 16, %2;"
                 :: "r"(dst), "l"(src), "r"(sz));
}
__device__ __forceinline__ void cpcommit() {
    asm volatile("cp.async.commit_group;" ::: "memory");
}
__device__ __forceinline__ void cpwait0() { asm volatile("cp.async.wait_group 0;" ::: "memory"); }

__device__ __forceinline__ void silu_split8_store(
        __nv_bfloat16* hiA, __nv_bfloat16* loA, size_t idx, const float* y) {
    U8b hi, lo;
#pragma unroll
    for (int j = 0; j < 8; j++) {
        float s = silu_f(y[j]);
        hi.b[j] = __float2bfloat16(s);
        lo.b[j] = __float2bfloat16(s - __bfloat162float(hi.b[j]));
    }
    *(uint4*)(hiA + idx) = hi.v;
    *(uint4*)(loA + idx) = lo.v;
}

// B chunk [128 n x 64 k] hi+lo -> swizzled smem
template<int NT>
__device__ __forceinline__ void prefB(uint32_t bufU,
        const __nv_bfloat16* __restrict__ wh, const __nv_bfloat16* __restrict__ wl,
        int KDIM, int kb, int tid) {
#pragma unroll
    for (int it = 0; it < 2048 / NT; ++it) {
        int i = tid + it * NT;
        int g = i & 7, n = (i >> 3) & 127, hl = i >> 10;
        const __nv_bfloat16* src = (hl ? wl : wh) + n * KDIM + kb + g * 8;
        uint32_t dst = bufU + hl * 16384 + n * 128 + ((g ^ (n & 7)) << 4);
        cpasync16(dst, src);
    }
}

// A chunk [64 rows x 64 k] hi+lo from pre-split act arrays (256 threads)
__device__ __forceinline__ void prefA64(uint32_t bufU,
        const __nv_bfloat16* __restrict__ aHi, const __nv_bfloat16* __restrict__ aLo,
        int KD, int Mtot, int mt, int kb, int tid) {
#pragma unroll
    for (int it = 0; it < 4; ++it) {
        int i = tid + it * 256;
        int g = i & 7, row = (i >> 3) & 63, hl = i >> 9;
        int mrow = mt * 64 + row;
        bool v = mrow < Mtot;
        const __nv_bfloat16* src = (hl ? aLo : aHi)
                                 + (size_t)(v ? mrow : 0) * KD + kb + g * 8;
        uint32_t dst = bufU + hl * 8192 + row * 128 + ((g ^ (row & 7)) << 4);
        cpasync16z(dst, src, v);
    }
}

// R=1 x T=8 over one 64-col chunk. RT row-tiles (rt in [0,RT)), cg colgroups.
template<int DUMMY>
__device__ __forceinline__ void mma_r1t8(
    float (&acc)[8][4],
    uint32_t aHiU, uint32_t aLoU, uint32_t bHiU, uint32_t bLoU,
    int rt, int cg, int lane)
{
    const int a_rowoff = (lane & 7) + (((lane >> 3) & 1) << 3);
    const int a_koff   = (lane >> 4) << 3;
    const int b_nl     = lane & 7;
    const int b_koff   = ((lane >> 3) & 1) << 3;
    const int b_nts    = lane >> 4;
#pragma unroll
    for (int kq = 0; kq < 64; kq += 16) {
        int Rr = rt * 16 + a_rowoff;
        int kc = kq + a_koff;
        int offs = Rr * 128 + (((kc >> 3) ^ (Rr & 7)) << 4);
        uint32_t aH[4], aL[4];
        ldmx4(aH, aHiU + offs);
        ldmx4(aL, aLoU + offs);
#pragma unroll
        for (int tp = 0; tp < 4; tp++) {
            int n = (cg * 8 + tp * 2 + b_nts) * 8 + b_nl;
            int cs = ((kq + b_koff) >> 3) ^ (n & 7);
            uint32_t boff = (uint32_t)(n * 128 + (cs << 4));
            uint32_t bH[4], bL[4];
            ldmx4(bH, bHiU + boff);
            ldmx4(bL, bLoU + boff);
#pragma unroll
            for (int sub = 0; sub < 2; sub++) {
                float* cc = acc[tp * 2 + sub];
                mma16816(cc, aH, bH[2*sub], bH[2*sub+1]);
                mma16816(cc, aL, bH[2*sub], bH[2*sub+1]);
                mma16816(cc, aH, bL[2*sub], bL[2*sub+1]);
            }
        }
    }
}

// ===========================================================================
// G01: fused stage0 (Y GEMM, 136 pairs + pad) + stage1 (window GEMM), per
// (mt, bh). 512 threads.
// SMEM: A1 bufs @0,36864 (144 rows x 128B; hi+0, lo+18432)
//       B  bufs @73728,106496  ([128n x 64k]; hi/lo +16384)
//       pew @139264 (8KB)
//       A2 bufs @147456,180224 ([128 rows x 64k]; hi/lo +16384)
//       ybuf fp32 [136][132] overlays A1 region after phase 1.
// ===========================================================================
#define P1_A(b)   ((b) * 36864)
#define P1_B(b)   (73728 + (b) * 32768)
#define G01_PEW   139264
#define P2_A(b)   (147456 + (b) * 32768)
#define G01_SMEM  212992
#define YSTR      132

__device__ __forceinline__ void g01_stsA1(char* sm, int bufByte, const float4* rA,
                                          int tid) {
#pragma unroll
    for (int t = 0; t < 5; ++t) {
        int idx = tid + t * 512;
        if (idx < 2304) {
            int row = idx >> 4, fc = idx & 15;
            float v[4] = {rA[t].x, rA[t].y, rA[t].z, rA[t].w};
            U4b hi, lo;
#pragma unroll
            for (int j = 0; j < 4; j++) {
                hi.b[j] = __float2bfloat16(v[j]);
                lo.b[j] = __float2bfloat16(v[j] - __bfloat162float(hi.b[j]));
            }
            int g = fc >> 1;
            int off = bufByte + row * 128 + ((g ^ (row & 7)) << 4) + (fc & 1) * 8;
            *(unsigned long long*)(sm + off)         = hi.u;
            *(unsigned long long*)(sm + off + 18432) = lo.u;
        }
    }
}

__device__ __forceinline__ void g01_ldgA1(float4* rA, const float* __restrict__ kB,
                                          int pairBase, int ch, int tid) {
#pragma unroll
    for (int t = 0; t < 5; ++t) {
        int idx = tid + t * 512;
        rA[t] = make_float4(0.f, 0.f, 0.f, 0.f);
        if (idx < 2304) {
            int row = idx >> 4, fc = idx & 15;
            if (row < 136 && pairBase + row < 4096)
                rA[t] = *(const float4*)(kB + (size_t)(pairBase + row) * 256
                                         + ch * 64 + 4 * fc);
        }
    }
}

// phase-2 A staging: silu(ybuf + pew) -> split bf16 -> swizzled A2 chunk
__device__ __forceinline__ void g01_stageA2(char* sm, int bufByte, int ch, int tid) {
    const float* ybuf = (const float*)sm;
    const float* pews = (const float*)(sm + G01_PEW);
    const int bsel = ch >> 1, d0 = (ch & 1) * 64;
#pragma unroll
    for (int it = 0; it < 2; ++it) {
        int idx = tid + it * 512;               // 1024 units of 8 cols
        int m = idx >> 3, blk = idx & 7;
        int r = 2 * (m & 7) + bsel;
        int jr = 8 * (m >> 3) + r;
        int cc0 = blk * 8;
        const float* ys = ybuf + jr * YSTR + d0 + cc0;
        const float* ps = pews + r * 128 + d0 + cc0;
        float y[8];
#pragma unroll
        for (int q = 0; q < 8; q += 2) {
            float2 a = *(const float2*)(ys + q);
            float2 p = *(const float2*)(ps + q);
            y[q] = a.x + p.x; y[q+1] = a.y + p.y;
        }
        U8b hi, lo;
#pragma unroll
        for (int j = 0; j < 8; j++) {
            float s = silu_f(y[j]);
            hi.b[j] = __float2bfloat16(s);
            lo.b[j] = __float2bfloat16(s - __bfloat162float(hi.b[j]));
        }
        int off = bufByte + m * 128 + ((blk ^ (m & 7)) << 4);
        *(uint4*)(sm + off)         = hi.v;
        *(uint4*)(sm + off + 16384) = lo.v;
    }
}

__global__ void __launch_bounds__(512, 1)
g01_kernel(const float* __restrict__ k)
{
    extern __shared__ char sm[];
    const uint32_t sb = u32p(sm);
    float* pews = (float*)(sm + G01_PEW);
    const int mt = blockIdx.x, bh = blockIdx.y;
    const int tid = threadIdx.x, lane = tid & 31, wid = tid >> 5;
    const int rt = wid & 7, cg = wid >> 3;
    const int pairBase = 128 * mt;
    const float* kB = k + (size_t)bh * S_LEN * 128;

    float acc[8][4];
#pragma unroll
    for (int t = 0; t < 8; t++)
#pragma unroll
        for (int j = 0; j < 4; j++) acc[t][j] = 0.f;
    float acc2[4] = {0.f, 0.f, 0.f, 0.f};

    ((float4*)pews)[tid] = ((const float4*)g_pew)[tid];

    // ---- phase 1 prologue ----
    {
        float4 rA[5];
        g01_ldgA1(rA, kB, pairBase, 0, tid);
        prefB<512>(sb + P1_B(0), g_w_hi, g_w_lo, 256, 0, tid);
        cpcommit();
        g01_stsA1(sm, P1_A(0), rA, tid);
    }
    cpwait0(); __syncthreads();

    // extra-tile lane constants
    const int a_rowoff = (lane & 7) + (((lane >> 3) & 1) << 3);
    const int a_koff   = (lane >> 4) << 3;
    const int xg       = lane >> 3;          // k-major B group
    const int xn       = wid * 8 + (lane & 7);

    for (int c = 0; c < 4; ++c) {
        float4 rA[5];
        if (c < 3) {
            g01_ldgA1(rA, kB, pairBase, c + 1, tid);
            prefB<512>(sb + P1_B((c + 1) & 1), g_w_hi, g_w_lo, 256, (c + 1) * 64, tid);
            cpcommit();
        }
        const uint32_t aU = sb + P1_A(c & 1);
        const uint32_t bU = sb + P1_B(c & 1);
        mma_r1t8<0>(acc, aU, aU + 18432, bU, bU + 16384, rt, cg, lane);
        // extra tile rows 128..143, n-tile = wid
#pragma unroll
        for (int kqb = 0; kqb < 64; kqb += 32) {
            uint32_t bH4[4], bL4[4];
            {
                int gg = (kqb >> 3) + xg;
                uint32_t boff = (uint32_t)(xn * 128 + ((gg ^ (xn & 7)) << 4));
                ldmx4(bH4, bU + boff);
                ldmx4(bL4, bU + 16384 + boff);
            }
#pragma unroll
            for (int s = 0; s < 2; ++s) {
                int kq = kqb + s * 16;
                int Rr = 128 + a_rowoff;
                int kc = kq + a_koff;
                int offs = Rr * 128 + (((kc >> 3) ^ (Rr & 7)) << 4);
                uint32_t aH[4], aL[4];
                ldmx4(aH, aU + offs);
                ldmx4(aL, aU + 18432 + offs);
                mma16816(acc2, aH, bH4[2*s], bH4[2*s+1]);
                mma16816(acc2, aL, bH4[2*s], bH4[2*s+1]);
                mma16816(acc2, aH, bL4[2*s], bL4[2*s+1]);
            }
        }
        if (c < 3) {
            g01_stsA1(sm, P1_A((c + 1) & 1), rA, tid);
            cpwait0();
        }
        __syncthreads();
    }

    // ---- phase-1 epilogue: Y -> ybuf fp32 ----
    float* ybuf = (float*)sm;
    const int r0 = lane >> 2, cof = (lane & 3) << 1;
#pragma unroll
    for (int t = 0; t < 8; t++) {
        int col = cg * 64 + t * 8 + cof;
#pragma unroll
        for (int h = 0; h < 2; h++) {
            int row = rt * 16 + r0 + (h << 3);
            *(float2*)(ybuf + row * YSTR + col) =
                make_float2(acc[t][2*h], acc[t][2*h+1]);
        }
    }
    {   // extra rows 128..135 (h=0 only)
        int col = wid * 8 + cof;
        int row = 128 + r0;
        *(float2*)(ybuf + row * YSTR + col) = make_float2(acc2[0], acc2[1]);
    }
    __syncthreads();

    // ---- phase 2 ----
#pragma unroll
    for (int t = 0; t < 8; t++)
#pragma unroll
        for (int j = 0; j < 4; j++) acc[t][j] = 0.f;

    g01_stageA2(sm, P2_A(0), 0, tid);
    prefB<512>(sb + P1_B(0), g_w_hi + 32768, g_w_lo + 32768, 256, 0, tid);
    cpcommit();

    for (int c = 0; c < 4; ++c) {
        cpwait0();
        __syncthreads();
        if (c < 3) {
            prefB<512>(sb + P1_B((c + 1) & 1), g_w_hi + 32768, g_w_lo + 32768,
                       256, (c + 1) * 64, tid);
            cpcommit();
            g01_stageA2(sm, P2_A((c + 1) & 1), c + 1, tid);
        }
        const uint32_t aU = sb + P2_A(c & 1);
        const uint32_t bU = sb + P1_B(c & 1);
        mma_r1t8<0>(acc, aU, aU + 16384, bU, bU + 16384, rt, cg, lane);
    }

    // ---- phase-2 epilogue: transpose via ybuf, coalesced a1 store ----
    // (last compute reads A2/B only; ybuf free to overwrite, sync before read)
#pragma unroll
    for (int t = 0; t < 8; t++) {
        int col = cg * 64 + t * 8 + cof;
#pragma unroll
        for (int h = 0; h < 2; h++) {
            int row = rt * 16 + r0 + (h << 3);
            *(float2*)(ybuf + row * YSTR + col) =
                make_float2(acc[t][2*h], acc[t][2*h+1]);
        }
    }
    __syncthreads();

    const int mMax = (mt == 31) ? 120 : 128;
    const size_t a1base = ((size_t)bh * NWIN + 16 * mt) * 8;
#pragma unroll
    for (int it = 0; it < 4; ++it) {
        int idx = tid + it * 512;               // 2048 units: 128 rows x 16 blocks
        int m = idx >> 4, cb = (idx & 15) << 3;
        if (m < mMax) {
            const float* ys = ybuf + m * YSTR + cb;
            float y[8];
#pragma unroll
            for (int q = 0; q < 8; q += 2) {
                float2 a = *(const float2*)(ys + q);
                y[q] = a.x; y[q+1] = a.y;
            }
            silu_split8_store(g_a1_hi, g_a1_lo, (a1base + m) * 128 + cb, y);
        }
    }
}

// ===========================================================================
// G2,G3 (r12 proven): 256-thr, M=64, 2 CTAs/SM, transpose epilogue.
// ===========================================================================
#define GS_SMEM 98304

template<int STAGE>
__global__ void __launch_bounds__(256, 2)
gstage_kernel()
{
    const __nv_bfloat16 *aHi, *aLo, *wh, *wl;
    __nv_bfloat16 *oHi, *oLo;
    int Mtot;
    if constexpr (STAGE == 2) { aHi=g_a1_hi; aLo=g_a1_lo; wh=g_w_hi+65536; wl=g_w_lo+65536; oHi=g_a2_hi; oLo=g_a2_lo; Mtot=M2; }
    if constexpr (STAGE == 3) { aHi=g_a2_hi; aLo=g_a2_lo; wh=g_w_hi+98304; wl=g_w_lo+98304; oHi=g_a3_hi; oLo=g_a3_lo; Mtot=M3; }

    extern __shared__ char sm[];
    const uint32_t sb = u32p(sm);
    const int mt = blockIdx.x;
    const int tid = threadIdx.x, lane = tid & 31, wid = tid >> 5;
    const int rt = wid & 3, cg = wid >> 2;

    float acc[8][4];
#pragma unroll
    for (int t = 0; t < 8; t++)
#pragma unroll
        for (int j = 0; j < 4; j++) acc[t][j] = 0.f;

    prefA64(sb, aHi, aLo, 256, Mtot, mt, 0, tid);
    prefB<256>(sb + 32768, wh, wl, 256, 0, tid);
    cpcommit();

    for (int c = 0; c < 4; ++c) {
        cpwait0();
        __syncthreads();
        if (c + 1 < 4) {
            int b = (c + 1) & 1;
            prefA64(sb + b * 16384, aHi, aLo, 256, Mtot, mt, (c + 1) * 64, tid);
            prefB<256>(sb + 32768 + b * 32768, wh, wl, 256, (c + 1) * 64, tid);
            cpcommit();
        }
        const uint32_t aU = sb + (c & 1) * 16384;
        const uint32_t bU = sb + 32768 + (c & 1) * 32768;
        mma_r1t8<0>(acc, aU, aU + 8192, bU, bU + 16384, rt, cg, lane);
    }
    __syncthreads();

    float* ybuf = (float*)sm;
    const int r0 = lane >> 2, cof = (lane & 3) << 1;
#pragma unroll
    for (int t = 0; t < 8; t++) {
        int col = (cg * 8 + t) * 8 + cof;
#pragma unroll
        for (int h = 0; h < 2; h++) {
            int r = rt * 16 + r0 + (h << 3);
            *(float2*)(ybuf + r * YSTR + col) = make_float2(acc[t][2*h], acc[t][2*h+1]);
        }
    }
    __syncthreads();

#pragma unroll
    for (int it = 0; it < 4; ++it) {
        int idx = tid + it * 256;               // 1024 units
        int row = idx >> 4, cb = (idx & 15) << 3;
        int m = mt * 64 + row;
        if (m < Mtot) {
            const float* ys = ybuf + row * YSTR + cb;
            float y[8];
#pragma unroll
            for (int q = 0; q < 8; q += 2) {
                float2 a = *(const float2*)(ys + q);
                y[q] = a.x; y[q+1] = a.y;
            }
            silu_split8_store(oHi, oLo, (size_t)m * 128 + cb, y);
        }
    }
}

// ===========================================================================
// G45 (r12 proven): stage 4 + stage 5 fused; 2 CTAs/SM.
// ===========================================================================
__global__ void __launch_bounds__(256, 2)
g45_kernel(float* __restrict__ gout)
{
    extern __shared__ char sm[];
    const uint32_t sb = u32p(sm);
    const int mt = blockIdx.x;
    const int tid = threadIdx.x, lane = tid & 31, wid = tid >> 5;
    const int rt = wid & 3, cg = wid >> 2;
    const int r0 = lane >> 2, cof = (lane & 3) << 1;

    float acc[8][4];
#pragma unroll
    for (int t = 0; t < 8; t++)
#pragma unroll
        for (int j = 0; j < 4; j++) acc[t][j] = 0.f;

    prefA64(sb, g_a3_hi, g_a3_lo, 256, M4, mt, 0, tid);
    prefB<256>(sb + 32768, g_w_hi + 131072, g_w_lo + 131072, 256, 0, tid);
    cpcommit();
    for (int c = 0; c < 4; ++c) {
        cpwait0();
        __syncthreads();
        if (c + 1 < 4) {
            int b = (c + 1) & 1;
            prefA64(sb + b * 16384, g_a3_hi, g_a3_lo, 256, M4, mt, (c + 1) * 64, tid);
            prefB<256>(sb + 32768 + b * 32768, g_w_hi + 131072, g_w_lo + 131072,
                       256, (c + 1) * 64, tid);
            cpcommit();
        }
        const uint32_t aU = sb + (c & 1) * 16384;
        const uint32_t bU = sb + 32768 + (c & 1) * 32768;
        mma_r1t8<0>(acc, aU, aU + 8192, bU, bU + 16384, rt, cg, lane);
    }
    __syncthreads();

    prefB<256>(sb + 32768, g_w_hi + 163840, g_w_lo + 163840, 128, 0, tid);
    prefB<256>(sb + 65536, g_w_hi + 163840, g_w_lo + 163840, 128, 64, tid);
    cpcommit();
#pragma unroll
    for (int t = 0; t < 8; t++) {
        int col = (cg * 8 + t) * 8 + cof;
        float* cc = acc[t];
#pragma unroll
        for (int h = 0; h < 2; h++) {
            int r = rt * 16 + r0 + (h << 3);
            float v0 = silu_f(cc[2*h]), v1 = silu_f(cc[2*h + 1]);
            U2b hi, lo;
            hi.b[0] = __float2bfloat16(v0);
            hi.b[1] = __float2bfloat16(v1);
            lo.b[0] = __float2bfloat16(v0 - __bfloat162float(hi.b[0]));
            lo.b[1] = __float2bfloat16(v1 - __bfloat162float(hi.b[1]));
            int b = col >> 6, lc = col & 63, g = lc >> 3;
            int off = b * 16384 + r * 128 + ((g ^ (r & 7)) << 4) + (lc & 7) * 2;
            *(uint32_t*)(sm + off)        = hi.u;
            *(uint32_t*)(sm + off + 8192) = lo.u;
        }
    }
    cpwait0();
    __syncthreads();

    float acc5[8][4];
#pragma unroll
    for (int t = 0; t < 8; t++)
#pragma unroll
        for (int j = 0; j < 4; j++) acc5[t][j] = 0.f;
#pragma unroll
    for (int c = 0; c < 2; ++c) {
        const uint32_t aU = sb + c * 16384;
        const uint32_t bU = sb + 32768 + c * 32768;
        mma_r1t8<0>(acc5, aU, aU + 8192, bU, bU + 16384, rt, cg, lane);
    }

#pragma unroll
    for (int t = 0; t < 8; t++) {
        int col = (cg * 8 + t) * 8 + cof;
        float* cc = acc5[t];
#pragma unroll
        for (int h = 0; h < 2; h++) {
            int r = rt * 16 + r0 + (h << 3);
            int m = mt * 64 + r;
            if (m < M4) {
                int bh = m / NWIN, w = m % NWIN;
                *(float2*)(gout + ((size_t)bh * 512 + 1 + w) * 128 + col) =
                    make_float2(cc[2*h], cc[2*h + 1]);
            }
        }
    }
}

extern "C" void kernel_launch(void* const* d_in, const int* in_sizes, int n_in,
                              void* d_out, int out_size)
{
    const float* k  = (const float*)d_in[0];
    const float* pe = (const float*)d_in[1];
    const float* wd = (const float*)d_in[2];
    const float* ws = (const float*)d_in[3];
    float* out = (float*)d_out;

    prep_kernel<<<728, 256>>>(wd, ws, pe, out);

    cudaFuncSetAttribute(g01_kernel,
                         cudaFuncAttributeMaxDynamicSharedMemorySize, G01_SMEM);
    cudaFuncSetAttribute(gstage_kernel<2>,
                         cudaFuncAttributeMaxDynamicSharedMemorySize, GS_SMEM);
    cudaFuncSetAttribute(gstage_kernel<3>,
                         cudaFuncAttributeMaxDynamicSharedMemorySize, GS_SMEM);
    cudaFuncSetAttribute(g45_kernel,
                         cudaFuncAttributeMaxDynamicSharedMemorySize, GS_SMEM);

    g01_kernel<<<dim3(32, BH), 512, G01_SMEM>>>(k);               // 1024 CTAs
    gstage_kernel<2><<<(M2 + 63) / 64, 256, GS_SMEM>>>();         // 1022
    gstage_kernel<3><<<(M3 + 63) / 64, 256, GS_SMEM>>>();         // 511
    g45_kernel<<<(M4 + 63) / 64, 256, GS_SMEM>>>(out);            // 256
}

// round 15
// speedup vs baseline: 1.0642x; 1.0642x over previous
#include <cuda_runtime.h>
#include <cuda_bf16.h>
#include <cstdint>

#define S_LEN  8192
#define BH     32
#define NWIN   511
#define WTOT   (5*128*256 + 128*128)

#define M1 (BH*NWIN*8)   // 130816
#define M2 (BH*NWIN*4)   // 65408
#define M3 (BH*NWIN*2)   // 32704
#define M4 (BH*NWIN)     // 16352

__device__ __nv_bfloat16 g_w_hi[WTOT];
__device__ __nv_bfloat16 g_w_lo[WTOT];
__device__ float         g_pew[16 * 128];
__device__ __nv_bfloat16 g_a0_hi[(size_t)BH*NWIN*16*128], g_a0_lo[(size_t)BH*NWIN*16*128];
__device__ __nv_bfloat16 g_a1_hi[(size_t)M1*128], g_a1_lo[(size_t)M1*128];
__device__ __nv_bfloat16 g_a2_hi[(size_t)M2*128], g_a2_lo[(size_t)M2*128];
__device__ __nv_bfloat16 g_a3_hi[(size_t)M3*128], g_a3_lo[(size_t)M3*128];

union U8b { __nv_bfloat16 b[8]; uint4 v; };
union U4b { __nv_bfloat16 b[4]; unsigned long long u; };
union U2b { __nv_bfloat16 b[2]; uint32_t u; };

// ---------------------------------------------------------------------------
// merged prep: blocks [0,704) split weights; [704,712) pew; [712,728) zero out
__global__ void prep_kernel(const float* __restrict__ wd,
                            const float* __restrict__ ws,
                            const float* __restrict__ pe,
                            float* __restrict__ out) {
    int b = blockIdx.x, tid = threadIdx.x;
    if (b < 704) {
        int i = b * 256 + tid;
        if (i < WTOT) {
            float v = (i < 5*128*256) ? wd[i] : ws[i - 5*128*256];
            __nv_bfloat16 h = __float2bfloat16(v);
            g_w_hi[i] = h;
            g_w_lo[i] = __float2bfloat16(v - __bfloat162float(h));
        }
    } else if (b < 712) {
        int idx = (b - 704) * 256 + tid;       // 2048
        int n = idx >> 4, j = idx & 15;        // coalesced wd rows per warp
        float s = 0.f;
        for (int d = 0; d < 128; ++d) {
            s += pe[(2*j)*128 + d]   * wd[n*256 + d];
            s += pe[(2*j+1)*128 + d] * wd[n*256 + 128 + d];
        }
        g_pew[j * 128 + n] = s;
    } else {
        int i = (b - 712) * 256 + tid;
        if (i < 4096)
            out[(size_t)(i >> 7) * 512 * 128 + (i & 127)] = 0.f;
    }
}

// ---------------------------------------------------------------------------
__device__ __forceinline__ uint32_t u32p(const void* p) {
    return (uint32_t)__cvta_generic_to_shared(p);
}
__device__ __forceinline__ void ldmx4(uint32_t* r, uint32_t addr) {
    asm volatile("ldmatrix.sync.aligned.m8n8.x4.shared.b16 {%0,%1,%2,%3}, [%4];"
                 : "=r"(r[0]), "=r"(r[1]), "=r"(r[2]), "=r"(r[3]) : "r"(addr));
}
__device__ __forceinline__ void mma16816(float* c, const uint32_t* a,
                                         uint32_t b0, uint32_t b1) {
    asm volatile("mma.sync.aligned.m16n8k16.row.col.f32.bf16.bf16.f32 "
                 "{%0,%1,%2,%3}, {%4,%5,%6,%7}, {%8,%9}, {%0,%1,%2,%3};"
                 : "+f"(c[0]), "+f"(c[1]), "+f"(c[2]), "+f"(c[3])
                 : "r"(a[0]), "r"(a[1]), "r"(a[2]), "r"(a[3]), "r"(b0), "r"(b1));
}
__device__ __forceinline__ float silu_f(float x) { return x / (1.f + __expf(-x)); }

__device__ __forceinline__ void cpasync16(uint32_t dst, const void* src) {
    asm volatile("cp.async.cg.shared.global [%0], [%1], 16;" :: "r"(dst), "l"(src));
}
__device__ __forceinline__ void cpasync16z(uint32_t dst, const void* src, bool v) {
    int sz = v ? 16 : 0;
    asm volatile("cp.async.cg.shared.global [%0], [%1], 16, %2;"
                 :: "r"(dst), "l"(src), "r"(sz));
}
__device__ __forceinline__ void cpcommit() {
    asm volatile("cp.async.commit_group;" ::: "memory");
}
__device__ __forceinline__ void cpwait0() { asm volatile("cp.async.wait_group 0;" ::: "memory"); }

// silu + split 8 fp32 -> coalesced 16B hi/lo stores
__device__ __forceinline__ void silu_split8_store(
        __nv_bfloat16* hiA, __nv_bfloat16* loA, size_t idx, const float* y) {
    U8b hi, lo;
#pragma unroll
    for (int j = 0; j < 8; j++) {
        float s = silu_f(y[j]);
        hi.b[j] = __float2bfloat16(s);
        lo.b[j] = __float2bfloat16(s - __bfloat162float(hi.b[j]));
    }
    *(uint4*)(hiA + idx) = hi.v;
    *(uint4*)(loA + idx) = lo.v;
}

// B chunk [128 n x 64 k] hi+lo -> swizzled smem
template<int NT>
__device__ __forceinline__ void prefB(uint32_t bufU,
        const __nv_bfloat16* __restrict__ wh, const __nv_bfloat16* __restrict__ wl,
        int KDIM, int kb, int tid) {
#pragma unroll
    for (int it = 0; it < 2048 / NT; ++it) {
        int i = tid + it * NT;
        int g = i & 7, n = (i >> 3) & 127, hl = i >> 10;
        const __nv_bfloat16* src = (hl ? wl : wh) + n * KDIM + kb + g * 8;
        uint32_t dst = bufU + hl * 16384 + n * 128 + ((g ^ (n & 7)) << 4);
        cpasync16(dst, src);
    }
}

// A chunk [64 rows x 64 k] hi+lo from pre-split act arrays (256 threads)
__device__ __forceinline__ void prefA64(uint32_t bufU,
        const __nv_bfloat16* __restrict__ aHi, const __nv_bfloat16* __restrict__ aLo,
        int KD, int Mtot, int mt, int kb, int tid) {
#pragma unroll
    for (int it = 0; it < 4; ++it) {
        int i = tid + it * 256;
        int g = i & 7, row = (i >> 3) & 63, hl = i >> 9;
        int mrow = mt * 64 + row;
        bool v = mrow < Mtot;
        const __nv_bfloat16* src = (hl ? aLo : aHi)
                                 + (size_t)(v ? mrow : 0) * KD + kb + g * 8;
        uint32_t dst = bufU + hl * 8192 + row * 128 + ((g ^ (row & 7)) << 4);
        cpasync16z(dst, src, v);
    }
}

// R=2 x T=4 warp tile over one 64-col chunk (16 warps: 4 row x 4 colgroup)
__device__ __forceinline__ void mma_chunk64(
    float (&acc)[2][4][4],
    uint32_t aHiU, uint32_t aLoU, uint32_t bHiU, uint32_t bLoU,
    int rBeg, int ntBeg, int lane)
{
    const int a_mat    = lane >> 3;
    const int a_rowoff = (lane & 7) + ((a_mat & 1) << 3);
    const int a_koff   = (a_mat >> 1) << 3;
    const int b_nl     = lane & 7;
    const int b_km     = (lane >> 3) << 3;
#pragma unroll
    for (int kq = 0; kq < 64; kq += 32) {
        uint32_t aH[2][8], aL[2][8];
#pragma unroll
        for (int i = 0; i < 2; i++) {
            int Rr = (rBeg + i) * 16 + a_rowoff;
            int kc0 = kq + a_koff;
            int offs0 = Rr * 128 + (((kc0 >> 3) ^ (Rr & 7)) << 4);
            int offs1 = Rr * 128 + ((((kc0 + 16) >> 3) ^ (Rr & 7)) << 4);
            ldmx4(aH[i], aHiU + offs0);
            ldmx4(aH[i] + 4, aHiU + offs1);
            ldmx4(aL[i], aLoU + offs0);
            ldmx4(aL[i] + 4, aLoU + offs1);
        }
#pragma unroll
        for (int t = 0; t < 4; t++) {
            int n = ((ntBeg + t) << 3) + b_nl;
            int cs = ((kq + b_km) >> 3) ^ (n & 7);
            uint32_t boff = n * 128 + (cs << 4);
            uint32_t bH[4], bL[4];
            ldmx4(bH, bHiU + boff);
            ldmx4(bL, bLoU + boff);
#pragma unroll
            for (int i = 0; i < 2; i++) {
                float* cc = acc[i][t];
                mma16816(cc, aH[i], bH[0], bH[1]);
                mma16816(cc, aL[i], bH[0], bH[1]);
                mma16816(cc, aH[i], bL[0], bL[1]);
                mma16816(cc, aH[i] + 4, bH[2], bH[3]);
                mma16816(cc, aL[i] + 4, bH[2], bH[3]);
                mma16816(cc, aH[i] + 4, bL[2], bL[3]);
            }
        }
    }
}

// R=1 x T=8 warp tile (8 warps: 4 row x 2 colgroup)
__device__ __forceinline__ void mma_r1t8(
    float (&acc)[8][4],
    uint32_t aHiU, uint32_t aLoU, uint32_t bHiU, uint32_t bLoU,
    int rt, int cg, int lane)
{
    const int a_rowoff = (lane & 7) + (((lane >> 3) & 1) << 3);
    const int a_koff   = (lane >> 4) << 3;
    const int b_nl     = lane & 7;
    const int b_koff   = ((lane >> 3) & 1) << 3;
    const int b_nts    = lane >> 4;
#pragma unroll
    for (int kq = 0; kq < 64; kq += 16) {
        int Rr = rt * 16 + a_rowoff;
        int kc = kq + a_koff;
        int offs = Rr * 128 + (((kc >> 3) ^ (Rr & 7)) << 4);
        uint32_t aH[4], aL[4];
        ldmx4(aH, aHiU + offs);
        ldmx4(aL, aLoU + offs);
#pragma unroll
        for (int tp = 0; tp < 4; tp++) {
            int n = (cg * 8 + tp * 2 + b_nts) * 8 + b_nl;
            int cs = ((kq + b_koff) >> 3) ^ (n & 7);
            uint32_t boff = (uint32_t)(n * 128 + (cs << 4));
            uint32_t bH[4], bL[4];
            ldmx4(bH, bHiU + boff);
            ldmx4(bL, bLoU + boff);
#pragma unroll
            for (int sub = 0; sub < 2; sub++) {
                float* cc = acc[tp * 2 + sub];
                mma16816(cc, aH, bH[2*sub], bH[2*sub+1]);
                mma16816(cc, aL, bH[2*sub], bH[2*sub+1]);
                mma16816(cc, aH, bL[2*sub], bL[2*sub+1]);
            }
        }
    }
}

// ===========================================================================
// G0 (r12 proven): 512 threads, 128-pair tiles, transpose epilogue.
// smem: A0 @0 (hi/lo 16384), A1 @32768; B @65536,98304; pew @131072.
// Epilogue ybuf: fp32 [128][132] overlays A region after final sync.
// ===========================================================================
#define G0_OFFB(b) (65536 + (b)*32768)
#define G0_PEW     131072
#define G0_SMEM    (131072 + 8192)
#define YSTR       132

__device__ __forceinline__ void g0_sts_A(char* sm, int bufByte, const float4* rA,
                                         int tid) {
#pragma unroll
    for (int t = 0; t < 4; ++t) {
        int f = tid + t * 512, row = f >> 4, fc = f & 15;
        float v[4] = {rA[t].x, rA[t].y, rA[t].z, rA[t].w};
        U4b hi, lo;
#pragma unroll
        for (int j = 0; j < 4; j++) {
            hi.b[j] = __float2bfloat16(v[j]);
            lo.b[j] = __float2bfloat16(v[j] - __bfloat162float(hi.b[j]));
        }
        int g = fc >> 1;
        int off = bufByte + row * 128 + ((g ^ (row & 7)) << 4) + (fc & 1) * 8;
        *(unsigned long long*)(sm + off)         = hi.u;
        *(unsigned long long*)(sm + off + 16384) = lo.u;
    }
}

__global__ void __launch_bounds__(512, 1)
g0_kernel(const float* __restrict__ k)
{
    extern __shared__ char sm[];
    const uint32_t sb = u32p(sm);
    float* pews = (float*)(sm + G0_PEW);
    const int mt = blockIdx.x, bh = blockIdx.y;
    const int tid = threadIdx.x, lane = tid & 31, wid = tid >> 5;
    const int rBeg = (wid & 3) * 2;
    const int cg   = wid >> 2;
    const float* Abase = k + (size_t)bh * S_LEN * 128 + (size_t)mt * 128 * 256;

    float acc[2][4][4];
#pragma unroll
    for (int i = 0; i < 2; i++)
#pragma unroll
        for (int t = 0; t < 4; t++)
#pragma unroll
            for (int j = 0; j < 4; j++) acc[i][t][j] = 0.f;

    ((float4*)pews)[tid] = ((const float4*)g_pew)[tid];

    // prologue: A0 (LDG/split/STS) + B0 (cp.async)
    {
        float4 rA[4];
#pragma unroll
        for (int t = 0; t < 4; ++t) {
            int f = tid + t * 512, row = f >> 4, fc = f & 15;
            rA[t] = *(const float4*)(Abase + (size_t)row * 256 + 4 * fc);
        }
        prefB<512>(sb + G0_OFFB(0), g_w_hi, g_w_lo, 256, 0, tid);
        cpcommit();
        g0_sts_A(sm, 0, rA, tid);
    }
    cpwait0(); __syncthreads();

    for (int c = 0; c < 4; ++c) {
        float4 rA[4];
        if (c < 3) {
#pragma unroll
            for (int t = 0; t < 4; ++t) {
                int f = tid + t * 512, row = f >> 4, fc = f & 15;
                rA[t] = *(const float4*)(Abase + (size_t)row * 256 + (c + 1) * 64 + 4 * fc);
            }
            prefB<512>(sb + G0_OFFB((c + 1) & 1), g_w_hi, g_w_lo, 256, (c + 1) * 64, tid);
            cpcommit();
        }
        const uint32_t aU = sb + (c & 1) * 32768;
        const uint32_t bU = sb + G0_OFFB(c & 1);
        mma_chunk64(acc, aU, aU + 16384, bU, bU + 16384, rBeg, cg * 4, lane);
        if (c < 3) {
            g0_sts_A(sm, ((c + 1) & 1) * 32768, rA, tid);
            cpwait0();
        }
        __syncthreads();
    }

    // ---- transpose epilogue ----
    float* ybuf = (float*)sm;     // [128][132] fp32
    const int r0 = lane >> 2, cof = (lane & 3) << 1;
#pragma unroll
    for (int i = 0; i < 2; i++)
#pragma unroll
        for (int t = 0; t < 4; t++) {
            int col = (cg * 4 + t) * 8 + cof;
            float* cc = acc[i][t];
#pragma unroll
            for (int h = 0; h < 2; h++) {
                int r = (rBeg + i) * 16 + r0 + (h << 3);
                *(float2*)(ybuf + r * YSTR + col) = make_float2(cc[2*h], cc[2*h+1]);
            }
        }
    __syncthreads();

    const size_t bhbase = (size_t)bh * NWIN;
#pragma unroll
    for (int it = 0; it < 4; ++it) {
        int idx = tid + it * 512;            // 2048 units: 128 rows x 16 blocks
        int row = idx >> 4, cb = (idx & 15) << 3;
        float4 va = *(const float4*)(ybuf + row * YSTR + cb);
        float4 vb = *(const float4*)(ybuf + row * YSTR + cb + 4);
        float y[8] = {va.x, va.y, va.z, va.w, vb.x, vb.y, vb.z, vb.w};
        int j = mt * 128 + row;
        int w1 = j >> 3, ra = j & 7;
        if (w1 < NWIN) {
            const float* bp = pews + ra * 128 + cb;
            float z[8];
#pragma unroll
            for (int q = 0; q < 8; q++) z[q] = y[q] + bp[q];
            silu_split8_store(g_a0_hi, g_a0_lo,
                ((bhbase + w1) * 16 + ra) * 128 + cb, z);
        }
        if (w1 >= 1) {
            const float* bp = pews + (8 + ra) * 128 + cb;
            float z[8];
#pragma unroll
            for (int q = 0; q < 8; q++) z[q] = y[q] + bp[q];
            silu_split8_store(g_a0_hi, g_a0_lo,
                ((bhbase + (w1 - 1)) * 16 + 8 + ra) * 128 + cb, z);
        }
    }
}

// ===========================================================================
// G1..G3 (r12 proven): 256-thr, M=64, 96KB -> 2 CTAs/SM, transpose epilogue.
// ===========================================================================
#define GS_SMEM 98304

template<int STAGE>
__global__ void __launch_bounds__(256, 2)
gstage_kernel()
{
    const __nv_bfloat16 *aHi, *aLo, *wh, *wl;
    __nv_bfloat16 *oHi, *oLo;
    int Mtot;
    if constexpr (STAGE == 1) { aHi=g_a0_hi; aLo=g_a0_lo; wh=g_w_hi+32768; wl=g_w_lo+32768; oHi=g_a1_hi; oLo=g_a1_lo; Mtot=M1; }
    if constexpr (STAGE == 2) { aHi=g_a1_hi; aLo=g_a1_lo; wh=g_w_hi+65536; wl=g_w_lo+65536; oHi=g_a2_hi; oLo=g_a2_lo; Mtot=M2; }
    if constexpr (STAGE == 3) { aHi=g_a2_hi; aLo=g_a2_lo; wh=g_w_hi+98304; wl=g_w_lo+98304; oHi=g_a3_hi; oLo=g_a3_lo; Mtot=M3; }

    extern __shared__ char sm[];
    const uint32_t sb = u32p(sm);
    const int mt = blockIdx.x;
    const int tid = threadIdx.x, lane = tid & 31, wid = tid >> 5;
    const int rt = wid & 3, cg = wid >> 2;

    float acc[8][4];
#pragma unroll
    for (int t = 0; t < 8; t++)
#pragma unroll
        for (int j = 0; j < 4; j++) acc[t][j] = 0.f;

    prefA64(sb, aHi, aLo, 256, Mtot, mt, 0, tid);
    prefB<256>(sb + 32768, wh, wl, 256, 0, tid);
    cpcommit();

    for (int c = 0; c < 4; ++c) {
        cpwait0();
        __syncthreads();
        if (c + 1 < 4) {
            int b = (c + 1) & 1;
            prefA64(sb + b * 16384, aHi, aLo, 256, Mtot, mt, (c + 1) * 64, tid);
            prefB<256>(sb + 32768 + b * 32768, wh, wl, 256, (c + 1) * 64, tid);
            cpcommit();
        }
        const uint32_t aU = sb + (c & 1) * 16384;
        const uint32_t bU = sb + 32768 + (c & 1) * 32768;
        mma_r1t8(acc, aU, aU + 8192, bU, bU + 16384, rt, cg, lane);
    }
    __syncthreads();   // all reads done; smem free

    // ---- transpose epilogue ----
    float* ybuf = (float*)sm;     // [64][132] fp32
    const int r0 = lane >> 2, cof = (lane & 3) << 1;
#pragma unroll
    for (int t = 0; t < 8; t++) {
        int col = (cg * 8 + t) * 8 + cof;
        float* cc = acc[t];
#pragma unroll
        for (int h = 0; h < 2; h++) {
            int r = rt * 16 + r0 + (h << 3);
            *(float2*)(ybuf + r * YSTR + col) = make_float2(cc[2*h], cc[2*h+1]);
        }
    }
    __syncthreads();

#pragma unroll
    for (int it = 0; it < 4; ++it) {
        int idx = tid + it * 256;            // 1024 units: 64 rows x 16 blocks
        int row = idx >> 4, cb = (idx & 15) << 3;
        int m = mt * 64 + row;
        if (m < Mtot) {
            float4 va = *(const float4*)(ybuf + row * YSTR + cb);
            float4 vb = *(const float4*)(ybuf + row * YSTR + cb + 4);
            float y[8] = {va.x, va.y, va.z, va.w, vb.x, vb.y, vb.z, vb.w};
            silu_split8_store(oHi, oLo, (size_t)m * 128 + cb, y);
        }
    }
}

// ===========================================================================
// G45 (r12 proven): stage 4 (K=256 from a3) + stage 5 (K=128, w_stop) fused.
// ===========================================================================
__global__ void __launch_bounds__(256, 2)
g45_kernel(float* __restrict__ gout)
{
    extern __shared__ char sm[];
    const uint32_t sb = u32p(sm);
    const int mt = blockIdx.x;
    const int tid = threadIdx.x, lane = tid & 31, wid = tid >> 5;
    const int rt = wid & 3, cg = wid >> 2;
    const int r0 = lane >> 2, cof = (lane & 3) << 1;

    float acc[8][4];
#pragma unroll
    for (int t = 0; t < 8; t++)
#pragma unroll
        for (int j = 0; j < 4; j++) acc[t][j] = 0.f;

    // ---- stage 4 ----
    prefA64(sb, g_a3_hi, g_a3_lo, 256, M4, mt, 0, tid);
    prefB<256>(sb + 32768, g_w_hi + 131072, g_w_lo + 131072, 256, 0, tid);
    cpcommit();
    for (int c = 0; c < 4; ++c) {
        cpwait0();
        __syncthreads();
        if (c + 1 < 4) {
            int b = (c + 1) & 1;
            prefA64(sb + b * 16384, g_a3_hi, g_a3_lo, 256, M4, mt, (c + 1) * 64, tid);
            prefB<256>(sb + 32768 + b * 32768, g_w_hi + 131072, g_w_lo + 131072,
                       256, (c + 1) * 64, tid);
            cpcommit();
        }
        const uint32_t aU = sb + (c & 1) * 16384;
        const uint32_t bU = sb + 32768 + (c & 1) * 32768;
        mma_r1t8(acc, aU, aU + 8192, bU, bU + 16384, rt, cg, lane);
    }
    __syncthreads();

    // ---- stage-5 staging: w_stop chunks; A = silu(acc4) split -> A bufs ----
    prefB<256>(sb + 32768, g_w_hi + 163840, g_w_lo + 163840, 128, 0, tid);
    prefB<256>(sb + 65536, g_w_hi + 163840, g_w_lo + 163840, 128, 64, tid);
    cpcommit();
#pragma unroll
    for (int t = 0; t < 8; t++) {
        int col = (cg * 8 + t) * 8 + cof;
        float* cc = acc[t];
#pragma unroll
        for (int h = 0; h < 2; h++) {
            int r = rt * 16 + r0 + (h << 3);
            float v0 = silu_f(cc[2*h]), v1 = silu_f(cc[2*h + 1]);
            U2b hi, lo;
            hi.b[0] = __float2bfloat16(v0);
            hi.b[1] = __float2bfloat16(v1);
            lo.b[0] = __float2bfloat16(v0 - __bfloat162float(hi.b[0]));
            lo.b[1] = __float2bfloat16(v1 - __bfloat162float(hi.b[1]));
            int b = col >> 6, lc = col & 63, g = lc >> 3;
            int off = b * 16384 + r * 128 + ((g ^ (r & 7)) << 4) + (lc & 7) * 2;
            *(uint32_t*)(sm + off)        = hi.u;
            *(uint32_t*)(sm + off + 8192) = lo.u;
        }
    }
    cpwait0();
    __syncthreads();

    // ---- stage 5: 2 resident chunks ----
    float acc5[8][4];
#pragma unroll
    for (int t = 0; t < 8; t++)
#pragma unroll
        for (int j = 0; j < 4; j++) acc5[t][j] = 0.f;
#pragma unroll
    for (int c = 0; c < 2; ++c) {
        const uint32_t aU = sb + c * 16384;
        const uint32_t bU = sb + 32768 + c * 32768;
        mma_r1t8(acc5, aU, aU + 8192, bU, bU + 16384, rt, cg, lane);
    }

    // final fp32 store
#pragma unroll
    for (int t = 0; t < 8; t++) {
        int col = (cg * 8 + t) * 8 + cof;
        float* cc = acc5[t];
#pragma unroll
        for (int h = 0; h < 2; h++) {
            int r = rt * 16 + r0 + (h << 3);
            int m = mt * 64 + r;
            if (m < M4) {
                int bh = m / NWIN, w = m % NWIN;
                *(float2*)(gout + ((size_t)bh * 512 + 1 + w) * 128 + col) =
                    make_float2(cc[2*h], cc[2*h + 1]);
            }
        }
    }
}

extern "C" void kernel_launch(void* const* d_in, const int* in_sizes, int n_in,
                              void* d_out, int out_size)
{
    const float* k  = (const float*)d_in[0];
    const float* pe = (const float*)d_in[1];
    const float* wd = (const float*)d_in[2];
    const float* ws = (const float*)d_in[3];
    float* out = (float*)d_out;

    prep_kernel<<<728, 256>>>(wd, ws, pe, out);

    cudaFuncSetAttribute(g0_kernel,
                         cudaFuncAttributeMaxDynamicSharedMemorySize, G0_SMEM);
    cudaFuncSetAttribute(gstage_kernel<1>,
                         cudaFuncAttributeMaxDynamicSharedMemorySize, GS_SMEM);
    cudaFuncSetAttribute(gstage_kernel<2>,
                         cudaFuncAttributeMaxDynamicSharedMemorySize, GS_SMEM);
    cudaFuncSetAttribute(gstage_kernel<3>,
                         cudaFuncAttributeMaxDynamicSharedMemorySize, GS_SMEM);
    cudaFuncSetAttribute(g45_kernel,
                         cudaFuncAttributeMaxDynamicSharedMemorySize, GS_SMEM);

    g0_kernel<<<dim3(32, BH), 512, G0_SMEM>>>(k);                 // 1024 CTAs
    gstage_kernel<1><<<(M1 + 63) / 64, 256, GS_SMEM>>>();         // 2044
    gstage_kernel<2><<<(M2 + 63) / 64, 256, GS_SMEM>>>();         // 1022
    gstage_kernel<3><<<(M3 + 63) / 64, 256, GS_SMEM>>>();         // 511
    g45_kernel<<<(M4 + 63) / 64, 256, GS_SMEM>>>(out);            // 256
}

// round 16
// speedup vs baseline: 1.1008x; 1.0344x over previous
#include <cuda_runtime.h>
#include <cuda_bf16.h>
#include <cstdint>

#define S_LEN  8192
#define BH     32
#define NWIN   511
#define WTOT   (5*128*256 + 128*128)

#define M1 (BH*NWIN*8)   // 130816
#define M2 (BH*NWIN*4)   // 65408
#define M3 (BH*NWIN*2)   // 32704
#define M4 (BH*NWIN)     // 16352

__device__ __nv_bfloat16 g_w_hi[WTOT];
__device__ __nv_bfloat16 g_w_lo[WTOT];
__device__ float         g_pew[16 * 128];
__device__ __nv_bfloat16 g_a0_hi[(size_t)BH*NWIN*16*128], g_a0_lo[(size_t)BH*NWIN*16*128];
__device__ __nv_bfloat16 g_a1_hi[(size_t)M1*128], g_a1_lo[(size_t)M1*128];
__device__ __nv_bfloat16 g_a2_hi[(size_t)M2*128], g_a2_lo[(size_t)M2*128];
__device__ __nv_bfloat16 g_a3_hi[(size_t)M3*128], g_a3_lo[(size_t)M3*128];

// ---------------------------------------------------------------------------
// merged prep: blocks [0,704) split weights; [704,712) pew; [712,728) zero out
__global__ void prep_kernel(const float* __restrict__ wd,
                            const float* __restrict__ ws,
                            const float* __restrict__ pe,
                            float* __restrict__ out) {
    int b = blockIdx.x, tid = threadIdx.x;
    if (b < 704) {
        int i = b * 256 + tid;
        if (i < WTOT) {
            float v = (i < 5*128*256) ? wd[i] : ws[i - 5*128*256];
            __nv_bfloat16 h = __float2bfloat16(v);
            g_w_hi[i] = h;
            g_w_lo[i] = __float2bfloat16(v - __bfloat162float(h));
        }
    } else if (b < 712) {
        int idx = (b - 704) * 256 + tid;       // 2048
        int n = idx >> 4, j = idx & 15;        // coalesced wd rows per warp
        float s = 0.f;
        for (int d = 0; d < 128; ++d) {
            s += pe[(2*j)*128 + d]   * wd[n*256 + d];
            s += pe[(2*j+1)*128 + d] * wd[n*256 + 128 + d];
        }
        g_pew[j * 128 + n] = s;
    } else {
        int i = (b - 712) * 256 + tid;
        if (i < 4096)
            out[(size_t)(i >> 7) * 512 * 128 + (i & 127)] = 0.f;
    }
}

// ---------------------------------------------------------------------------
__device__ __forceinline__ uint32_t u32p(const void* p) {
    return (uint32_t)__cvta_generic_to_shared(p);
}
__device__ __forceinline__ void ldmx4(uint32_t* r, uint32_t addr) {
    asm volatile("ldmatrix.sync.aligned.m8n8.x4.shared.b16 {%0,%1,%2,%3}, [%4];"
                 : "=r"(r[0]), "=r"(r[1]), "=r"(r[2]), "=r"(r[3]) : "r"(addr));
}
__device__ __forceinline__ void mma16816(float* c, const uint32_t* a,
                                         uint32_t b0, uint32_t b1) {
    asm volatile("mma.sync.aligned.m16n8k16.row.col.f32.bf16.bf16.f32 "
                 "{%0,%1,%2,%3}, {%4,%5,%6,%7}, {%8,%9}, {%0,%1,%2,%3};"
                 : "+f"(c[0]), "+f"(c[1]), "+f"(c[2]), "+f"(c[3])
                 : "r"(a[0]), "r"(a[1]), "r"(a[2]), "r"(a[3]), "r"(b0), "r"(b1));
}
__device__ __forceinline__ float silu_f(float x) { return x / (1.f + __expf(-x)); }

// cheap truncation split: 2 fp32 -> packed bf16x2 hi (bit-truncate) + lo (RN)
// hi2 = {trunc16(v1), trunc16(v0)}, lo2 = {bf16(v1-h1), bf16(v0-h0)}
__device__ __forceinline__ void split2(float v0, float v1,
                                       uint32_t& hi2, uint32_t& lo2) {
    uint32_t b0 = __float_as_uint(v0), b1 = __float_as_uint(v1);
    asm("prmt.b32 %0, %1, %2, 0x7632;" : "=r"(hi2) : "r"(b0), "r"(b1));
    float l0 = v0 - __uint_as_float(b0 & 0xFFFF0000u);
    float l1 = v1 - __uint_as_float(b1 & 0xFFFF0000u);
    asm("cvt.rn.bf16x2.f32 %0, %1, %2;" : "=r"(lo2) : "f"(l1), "f"(l0));
}

__device__ __forceinline__ void cpasync16(uint32_t dst, const void* src) {
    asm volatile("cp.async.cg.shared.global [%0], [%1], 16;" :: "r"(dst), "l"(src));
}
__device__ __forceinline__ void cpasync16z(uint32_t dst, const void* src, bool v) {
    int sz = v ? 16 : 0;
    asm volatile("cp.async.cg.shared.global [%0], [%1], 16, %2;"
                 :: "r"(dst), "l"(src), "r"(sz));
}
__device__ __forceinline__ void cpcommit() {
    asm volatile("cp.async.commit_group;" ::: "memory");
}
__device__ __forceinline__ void cpwait0() { asm volatile("cp.async.wait_group 0;" ::: "memory"); }

// silu + truncation-split 8 fp32 -> coalesced 16B hi/lo stores
__device__ __forceinline__ void silu_split8_store(
        __nv_bfloat16* hiA, __nv_bfloat16* loA, size_t idx, const float* y) {
    float s[8];
#pragma unroll
    for (int j = 0; j < 8; j++) s[j] = silu_f(y[j]);
    uint4 hi, lo;
    split2(s[0], s[1], hi.x, lo.x);
    split2(s[2], s[3], hi.y, lo.y);
    split2(s[4], s[5], hi.z, lo.z);
    split2(s[6], s[7], hi.w, lo.w);
    *(uint4*)(hiA + idx) = hi;
    *(uint4*)(loA + idx) = lo;
}

// B chunk [128 n x 64 k] hi+lo -> swizzled smem
template<int NT>
__device__ __forceinline__ void prefB(uint32_t bufU,
        const __nv_bfloat16* __restrict__ wh, const __nv_bfloat16* __restrict__ wl,
        int KDIM, int kb, int tid) {
#pragma unroll
    for (int it = 0; it < 2048 / NT; ++it) {
        int i = tid + it * NT;
        int g = i & 7, n = (i >> 3) & 127, hl = i >> 10;
        const __nv_bfloat16* src = (hl ? wl : wh) + n * KDIM + kb + g * 8;
        uint32_t dst = bufU + hl * 16384 + n * 128 + ((g ^ (n & 7)) << 4);
        cpasync16(dst, src);
    }
}

// A chunk [64 rows x 64 k] hi+lo from pre-split act arrays (256 threads)
__device__ __forceinline__ void prefA64(uint32_t bufU,
        const __nv_bfloat16* __restrict__ aHi, const __nv_bfloat16* __restrict__ aLo,
        int KD, int Mtot, int mt, int kb, int tid) {
#pragma unroll
    for (int it = 0; it < 4; ++it) {
        int i = tid + it * 256;
        int g = i & 7, row = (i >> 3) & 63, hl = i >> 9;
        int mrow = mt * 64 + row;
        bool v = mrow < Mtot;
        const __nv_bfloat16* src = (hl ? aLo : aHi)
                                 + (size_t)(v ? mrow : 0) * KD + kb + g * 8;
        uint32_t dst = bufU + hl * 8192 + row * 128 + ((g ^ (row & 7)) << 4);
        cpasync16z(dst, src, v);
    }
}

// R=2 x T=4 warp tile over one 64-col chunk (16 warps: 4 row x 4 colgroup)
__device__ __forceinline__ void mma_chunk64(
    float (&acc)[2][4][4],
    uint32_t aHiU, uint32_t aLoU, uint32_t bHiU, uint32_t bLoU,
    int rBeg, int ntBeg, int lane)
{
    const int a_mat    = lane >> 3;
    const int a_rowoff = (lane & 7) + ((a_mat & 1) << 3);
    const int a_koff   = (a_mat >> 1) << 3;
    const int b_nl     = lane & 7;
    const int b_km     = (lane >> 3) << 3;
#pragma unroll
    for (int kq = 0; kq < 64; kq += 32) {
        uint32_t aH[2][8], aL[2][8];
#pragma unroll
        for (int i = 0; i < 2; i++) {
            int Rr = (rBeg + i) * 16 + a_rowoff;
            int kc0 = kq + a_koff;
            int offs0 = Rr * 128 + (((kc0 >> 3) ^ (Rr & 7)) << 4);
            int offs1 = Rr * 128 + ((((kc0 + 16) >> 3) ^ (Rr & 7)) << 4);
            ldmx4(aH[i], aHiU + offs0);
            ldmx4(aH[i] + 4, aHiU + offs1);
            ldmx4(aL[i], aLoU + offs0);
            ldmx4(aL[i] + 4, aLoU + offs1);
        }
#pragma unroll
        for (int t = 0; t < 4; t++) {
            int n = ((ntBeg + t) << 3) + b_nl;
            int cs = ((kq + b_km) >> 3) ^ (n & 7);
            uint32_t boff = n * 128 + (cs << 4);
            uint32_t bH[4], bL[4];
            ldmx4(bH, bHiU + boff);
            ldmx4(bL, bLoU + boff);
#pragma unroll
            for (int i = 0; i < 2; i++) {
                float* cc = acc[i][t];
                mma16816(cc, aH[i], bH[0], bH[1]);
                mma16816(cc, aL[i], bH[0], bH[1]);
                mma16816(cc, aH[i], bL[0], bL[1]);
                mma16816(cc, aH[i] + 4, bH[2], bH[3]);
                mma16816(cc, aL[i] + 4, bH[2], bH[3]);
                mma16816(cc, aH[i] + 4, bL[2], bL[3]);
            }
        }
    }
}

// R=1 x T=8 warp tile (8 warps: 4 row x 2 colgroup)
__device__ __forceinline__ void mma_r1t8(
    float (&acc)[8][4],
    uint32_t aHiU, uint32_t aLoU, uint32_t bHiU, uint32_t bLoU,
    int rt, int cg, int lane)
{
    const int a_rowoff = (lane & 7) + (((lane >> 3) & 1) << 3);
    const int a_koff   = (lane >> 4) << 3;
    const int b_nl     = lane & 7;
    const int b_koff   = ((lane >> 3) & 1) << 3;
    const int b_nts    = lane >> 4;
#pragma unroll
    for (int kq = 0; kq < 64; kq += 16) {
        int Rr = rt * 16 + a_rowoff;
        int kc = kq + a_koff;
        int offs = Rr * 128 + (((kc >> 3) ^ (Rr & 7)) << 4);
        uint32_t aH[4], aL[4];
        ldmx4(aH, aHiU + offs);
        ldmx4(aL, aLoU + offs);
#pragma unroll
        for (int tp = 0; tp < 4; tp++) {
            int n = (cg * 8 + tp * 2 + b_nts) * 8 + b_nl;
            int cs = ((kq + b_koff) >> 3) ^ (n & 7);
            uint32_t boff = (uint32_t)(n * 128 + (cs << 4));
            uint32_t bH[4], bL[4];
            ldmx4(bH, bHiU + boff);
            ldmx4(bL, bLoU + boff);
#pragma unroll
            for (int sub = 0; sub < 2; sub++) {
                float* cc = acc[tp * 2 + sub];
                mma16816(cc, aH, bH[2*sub], bH[2*sub+1]);
                mma16816(cc, aL, bH[2*sub], bH[2*sub+1]);
                mma16816(cc, aH, bL[2*sub], bL[2*sub+1]);
            }
        }
    }
}

// ===========================================================================
// G0: 512 threads, 128-pair tiles, transpose epilogue, truncation split.
// smem: A0 @0 (hi/lo 16384), A1 @32768; B @65536,98304; pew @131072.
// ===========================================================================
#define G0_OFFB(b) (65536 + (b)*32768)
#define G0_PEW     131072
#define G0_SMEM    (131072 + 8192)
#define YSTR       132

__device__ __forceinline__ void g0_sts_A(char* sm, int bufByte, const float4* rA,
                                         int tid) {
#pragma unroll
    for (int t = 0; t < 4; ++t) {
        int f = tid + t * 512, row = f >> 4, fc = f & 15;
        uint32_t h0, l0, h1, l1;
        split2(rA[t].x, rA[t].y, h0, l0);
        split2(rA[t].z, rA[t].w, h1, l1);
        unsigned long long hu = (unsigned long long)h0 | ((unsigned long long)h1 << 32);
        unsigned long long lu = (unsigned long long)l0 | ((unsigned long long)l1 << 32);
        int g = fc >> 1;
        int off = bufByte + row * 128 + ((g ^ (row & 7)) << 4) + (fc & 1) * 8;
        *(unsigned long long*)(sm + off)         = hu;
        *(unsigned long long*)(sm + off + 16384) = lu;
    }
}

__global__ void __launch_bounds__(512, 1)
g0_kernel(const float* __restrict__ k)
{
    extern __shared__ char sm[];
    const uint32_t sb = u32p(sm);
    float* pews = (float*)(sm + G0_PEW);
    const int mt = blockIdx.x, bh = blockIdx.y;
    const int tid = threadIdx.x, lane = tid & 31, wid = tid >> 5;
    const int rBeg = (wid & 3) * 2;
    const int cg   = wid >> 2;
    const float* Abase = k + (size_t)bh * S_LEN * 128 + (size_t)mt * 128 * 256;

    float acc[2][4][4];
#pragma unroll
    for (int i = 0; i < 2; i++)
#pragma unroll
        for (int t = 0; t < 4; t++)
#pragma unroll
            for (int j = 0; j < 4; j++) acc[i][t][j] = 0.f;

    ((float4*)pews)[tid] = ((const float4*)g_pew)[tid];

    // prologue: A0 (LDG/split/STS) + B0 (cp.async)
    {
        float4 rA[4];
#pragma unroll
        for (int t = 0; t < 4; ++t) {
            int f = tid + t * 512, row = f >> 4, fc = f & 15;
            rA[t] = *(const float4*)(Abase + (size_t)row * 256 + 4 * fc);
        }
        prefB<512>(sb + G0_OFFB(0), g_w_hi, g_w_lo, 256, 0, tid);
        cpcommit();
        g0_sts_A(sm, 0, rA, tid);
    }
    cpwait0(); __syncthreads();

    for (int c = 0; c < 4; ++c) {
        float4 rA[4];
        if (c < 3) {
#pragma unroll
            for (int t = 0; t < 4; ++t) {
                int f = tid + t * 512, row = f >> 4, fc = f & 15;
                rA[t] = *(const float4*)(Abase + (size_t)row * 256 + (c + 1) * 64 + 4 * fc);
            }
            prefB<512>(sb + G0_OFFB((c + 1) & 1), g_w_hi, g_w_lo, 256, (c + 1) * 64, tid);
            cpcommit();
        }
        const uint32_t aU = sb + (c & 1) * 32768;
        const uint32_t bU = sb + G0_OFFB(c & 1);
        mma_chunk64(acc, aU, aU + 16384, bU, bU + 16384, rBeg, cg * 4, lane);
        if (c < 3) {
            g0_sts_A(sm, ((c + 1) & 1) * 32768, rA, tid);
            cpwait0();
        }
        __syncthreads();
    }

    // ---- transpose epilogue ----
    float* ybuf = (float*)sm;     // [128][132] fp32
    const int r0 = lane >> 2, cof = (lane & 3) << 1;
#pragma unroll
    for (int i = 0; i < 2; i++)
#pragma unroll
        for (int t = 0; t < 4; t++) {
            int col = (cg * 4 + t) * 8 + cof;
            float* cc = acc[i][t];
#pragma unroll
            for (int h = 0; h < 2; h++) {
                int r = (rBeg + i) * 16 + r0 + (h << 3);
                *(float2*)(ybuf + r * YSTR + col) = make_float2(cc[2*h], cc[2*h+1]);
            }
        }
    __syncthreads();

    const size_t bhbase = (size_t)bh * NWIN;
#pragma unroll
    for (int it = 0; it < 4; ++it) {
        int idx = tid + it * 512;            // 2048 units: 128 rows x 16 blocks
        int row = idx >> 4, cb = (idx & 15) << 3;
        float4 va = *(const float4*)(ybuf + row * YSTR + cb);
        float4 vb = *(const float4*)(ybuf + row * YSTR + cb + 4);
        float y[8] = {va.x, va.y, va.z, va.w, vb.x, vb.y, vb.z, vb.w};
        int j = mt * 128 + row;
        int w1 = j >> 3, ra = j & 7;
        if (w1 < NWIN) {
            const float* bp = pews + ra * 128 + cb;
            float z[8];
#pragma unroll
            for (int q = 0; q < 8; q++) z[q] = y[q] + bp[q];
            silu_split8_store(g_a0_hi, g_a0_lo,
                ((bhbase + w1) * 16 + ra) * 128 + cb, z);
        }
        if (w1 >= 1) {
            const float* bp = pews + (8 + ra) * 128 + cb;
            float z[8];
#pragma unroll
            for (int q = 0; q < 8; q++) z[q] = y[q] + bp[q];
            silu_split8_store(g_a0_hi, g_a0_lo,
                ((bhbase + (w1 - 1)) * 16 + 8 + ra) * 128 + cb, z);
        }
    }
}

// ===========================================================================
// G1..G3: 256-thr, M=64, 96KB -> 2 CTAs/SM, transpose epilogue.
// ===========================================================================
#define GS_SMEM 98304

template<int STAGE>
__global__ void __launch_bounds__(256, 2)
gstage_kernel()
{
    const __nv_bfloat16 *aHi, *aLo, *wh, *wl;
    __nv_bfloat16 *oHi, *oLo;
    int Mtot;
    if constexpr (STAGE == 1) { aHi=g_a0_hi; aLo=g_a0_lo; wh=g_w_hi+32768; wl=g_w_lo+32768; oHi=g_a1_hi; oLo=g_a1_lo; Mtot=M1; }
    if constexpr (STAGE == 2) { aHi=g_a1_hi; aLo=g_a1_lo; wh=g_w_hi+65536; wl=g_w_lo+65536; oHi=g_a2_hi; oLo=g_a2_lo; Mtot=M2; }
    if constexpr (STAGE == 3) { aHi=g_a2_hi; aLo=g_a2_lo; wh=g_w_hi+98304; wl=g_w_lo+98304; oHi=g_a3_hi; oLo=g_a3_lo; Mtot=M3; }

    extern __shared__ char sm[];
    const uint32_t sb = u32p(sm);
    const int mt = blockIdx.x;
    const int tid = threadIdx.x, lane = tid & 31, wid = tid >> 5;
    const int rt = wid & 3, cg = wid >> 2;

    float acc[8][4];
#pragma unroll
    for (int t = 0; t < 8; t++)
#pragma unroll
        for (int j = 0; j < 4; j++) acc[t][j] = 0.f;

    prefA64(sb, aHi, aLo, 256, Mtot, mt, 0, tid);
    prefB<256>(sb + 32768, wh, wl, 256, 0, tid);
    cpcommit();

    for (int c = 0; c < 4; ++c) {
        cpwait0();
        __syncthreads();
        if (c + 1 < 4) {
            int b = (c + 1) & 1;
            prefA64(sb + b * 16384, aHi, aLo, 256, Mtot, mt, (c + 1) * 64, tid);
            prefB<256>(sb + 32768 + b * 32768, wh, wl, 256, (c + 1) * 64, tid);
            cpcommit();
        }
        const uint32_t aU = sb + (c & 1) * 16384;
        const uint32_t bU = sb + 32768 + (c & 1) * 32768;
        mma_r1t8(acc, aU, aU + 8192, bU, bU + 16384, rt, cg, lane);
    }
    __syncthreads();   // all reads done; smem free

    // ---- transpose epilogue ----
    float* ybuf = (float*)sm;     // [64][132] fp32
    const int r0 = lane >> 2, cof = (lane & 3) << 1;
#pragma unroll
    for (int t = 0; t < 8; t++) {
        int col = (cg * 8 + t) * 8 + cof;
        float* cc = acc[t];
#pragma unroll
        for (int h = 0; h < 2; h++) {
            int r = rt * 16 + r0 + (h << 3);
            *(float2*)(ybuf + r * YSTR + col) = make_float2(cc[2*h], cc[2*h+1]);
        }
    }
    __syncthreads();

#pragma unroll
    for (int it = 0; it < 4; ++it) {
        int idx = tid + it * 256;            // 1024 units: 64 rows x 16 blocks
        int row = idx >> 4, cb = (idx & 15) << 3;
        int m = mt * 64 + row;
        if (m < Mtot) {
            float4 va = *(const float4*)(ybuf + row * YSTR + cb);
            float4 vb = *(const float4*)(ybuf + row * YSTR + cb + 4);
            float y[8] = {va.x, va.y, va.z, va.w, vb.x, vb.y, vb.z, vb.w};
            silu_split8_store(oHi, oLo, (size_t)m * 128 + cb, y);
        }
    }
}

// ===========================================================================
// G45: stage 4 (K=256 from a3) + stage 5 (K=128, w_stop) fused; 2 CTAs/SM.
// ===========================================================================
__global__ void __launch_bounds__(256, 2)
g45_kernel(float* __restrict__ gout)
{
    extern __shared__ char sm[];
    const uint32_t sb = u32p(sm);
    const int mt = blockIdx.x;
    const int tid = threadIdx.x, lane = tid & 31, wid = tid >> 5;
    const int rt = wid & 3, cg = wid >> 2;
    const int r0 = lane >> 2, cof = (lane & 3) << 1;

    float acc[8][4];
#pragma unroll
    for (int t = 0; t < 8; t++)
#pragma unroll
        for (int j = 0; j < 4; j++) acc[t][j] = 0.f;

    // ---- stage 4 ----
    prefA64(sb, g_a3_hi, g_a3_lo, 256, M4, mt, 0, tid);
    prefB<256>(sb + 32768, g_w_hi + 131072, g_w_lo + 131072, 256, 0, tid);
    cpcommit();
    for (int c = 0; c < 4; ++c) {
        cpwait0();
        __syncthreads();
        if (c + 1 < 4) {
            int b = (c + 1) & 1;
            prefA64(sb + b * 16384, g_a3_hi, g_a3_lo, 256, M4, mt, (c + 1) * 64, tid);
            prefB<256>(sb + 32768 + b * 32768, g_w_hi + 131072, g_w_lo + 131072,
                       256, (c + 1) * 64, tid);
            cpcommit();
        }
        const uint32_t aU = sb + (c & 1) * 16384;
        const uint32_t bU = sb + 32768 + (c & 1) * 32768;
        mma_r1t8(acc, aU, aU + 8192, bU, bU + 16384, rt, cg, lane);
    }
    __syncthreads();

    // ---- stage-5 staging: w_stop chunks; A = silu(acc4) split -> A bufs ----
    prefB<256>(sb + 32768, g_w_hi + 163840, g_w_lo + 163840, 128, 0, tid);
    prefB<256>(sb + 65536, g_w_hi + 163840, g_w_lo + 163840, 128, 64, tid);
    cpcommit();
#pragma unroll
    for (int t = 0; t < 8; t++) {
        int col = (cg * 8 + t) * 8 + cof;
        float* cc = acc[t];
#pragma unroll
        for (int h = 0; h < 2; h++) {
            int r = rt * 16 + r0 + (h << 3);
            float v0 = silu_f(cc[2*h]), v1 = silu_f(cc[2*h + 1]);
            uint32_t hu, lu;
            split2(v0, v1, hu, lu);
            int b = col >> 6, lc = col & 63, g = lc >> 3;
            int off = b * 16384 + r * 128 + ((g ^ (r & 7)) << 4) + (lc & 7) * 2;
            *(uint32_t*)(sm + off)        = hu;
            *(uint32_t*)(sm + off + 8192) = lu;
        }
    }
    cpwait0();
    __syncthreads();

    // ---- stage 5: 2 resident chunks ----
    float acc5[8][4];
#pragma unroll
    for (int t = 0; t < 8; t++)
#pragma unroll
        for (int j = 0; j < 4; j++) acc5[t][j] = 0.f;
#pragma unroll
    for (int c = 0; c < 2; ++c) {
        const uint32_t aU = sb + c * 16384;
        const uint32_t bU = sb + 32768 + c * 32768;
        mma_r1t8(acc5, aU, aU + 8192, bU, bU + 16384, rt, cg, lane);
    }

    // final fp32 store
#pragma unroll
    for (int t = 0; t < 8; t++) {
        int col = (cg * 8 + t) * 8 + cof;
        float* cc = acc5[t];
#pragma unroll
        for (int h = 0; h < 2; h++) {
            int r = rt * 16 + r0 + (h << 3);
            int m = mt * 64 + r;
            if (m < M4) {
                int bh = m / NWIN, w = m % NWIN;
                *(float2*)(gout + ((size_t)bh * 512 + 1 + w) * 128 + col) =
                    make_float2(cc[2*h], cc[2*h + 1]);
            }
        }
    }
}

extern "C" void kernel_launch(void* const* d_in, const int* in_sizes, int n_in,
                              void* d_out, int out_size)
{
    const float* k  = (const float*)d_in[0];
    const float* pe = (const float*)d_in[1];
    const float* wd = (const float*)d_in[2];
    const float* ws = (const float*)d_in[3];
    float* out = (float*)d_out;

    prep_kernel<<<728, 256>>>(wd, ws, pe, out);

    cudaFuncSetAttribute(g0_kernel,
                         cudaFuncAttributeMaxDynamicSharedMemorySize, G0_SMEM);
    cudaFuncSetAttribute(gstage_kernel<1>,
                         cudaFuncAttributeMaxDynamicSharedMemorySize, GS_SMEM);
    cudaFuncSetAttribute(gstage_kernel<2>,
                         cudaFuncAttributeMaxDynamicSharedMemorySize, GS_SMEM);
    cudaFuncSetAttribute(gstage_kernel<3>,
                         cudaFuncAttributeMaxDynamicSharedMemorySize, GS_SMEM);
    cudaFuncSetAttribute(g45_kernel,
                         cudaFuncAttributeMaxDynamicSharedMemorySize, GS_SMEM);

    g0_kernel<<<dim3(32, BH), 512, G0_SMEM>>>(k);                 // 1024 CTAs
    gstage_kernel<1><<<(M1 + 63) / 64, 256, GS_SMEM>>>();         // 2044
    gstage_kernel<2><<<(M2 + 63) / 64, 256, GS_SMEM>>>();         // 1022
    gstage_kernel<3><<<(M3 + 63) / 64, 256, GS_SMEM>>>();         // 511
    g45_kernel<<<(M4 + 63) / 64, 256, GS_SMEM>>>(out);            // 256
}